// round 5
// baseline (speedup 1.0000x reference)
#include <cuda_runtime.h>

// GainesEdgeDetect, first bit-cycle from fresh module state.
// Exact constant propagation (see R3 analysis): with sel=0, x in {0,1},
// and fresh FSUAbs counter cnt=HALF=8, the emitted abs-bit is identically 1.
// => pure constant fill of 1.0f over 16*1024*1024 floats (67.1 MB).
//
// R4: 8 float4 stores per thread (128 B/thread) to amortize launch/index
// overhead and keep the LSU fed with independent STG.128s.

#define F4_PER_THREAD 8

__global__ void gaines_edge_fill_kernel(float4* __restrict__ o4) {
    // Block covers blockDim.x * F4_PER_THREAD consecutive float4s,
    // coalesced: thread t writes t, t+256, t+512, ... within the block span.
    int base = blockIdx.x * (blockDim.x * F4_PER_THREAD) + threadIdx.x;
    const float4 v = make_float4(1.0f, 1.0f, 1.0f, 1.0f);
#pragma unroll
    for (int j = 0; j < F4_PER_THREAD; j++) {
        o4[base + j * 256] = v;
    }
}

extern "C" void kernel_launch(void* const* d_in, const int* in_sizes, int n_in,
                              void* d_out, int out_size) {
    float* out = (float*)d_out;

    int n4 = out_size / 4;                       // 4,194,304 float4s
    const int threads = 256;
    int f4_per_block = threads * F4_PER_THREAD;  // 2048
    int blocks = n4 / f4_per_block;              // 2048 (exact: 4194304/2048)

    gaines_edge_fill_kernel<<<blocks, threads>>>((float4*)out);
}

// round 6
// speedup vs baseline: 1.0201x; 1.0201x over previous
#include <cuda_runtime.h>
#include <cstdint>

// GainesEdgeDetect first bit-cycle: exact constant propagation (see R3) —
// output is identically 1.0f. 67.1 MB constant fill.
//
// R5 experiment: drive the stores through the TMA/bulk-copy engine
// (cp.async.bulk.global.shared::cta) instead of per-thread STG.128, to test
// whether the ~5.9 TB/s plateau seen in R3/R4 is an SM-side store limit
// (TMA should beat it) or the LTS write-port cap (neutral).

#define CHUNK_BYTES   32768              // 32 KB SMEM staging buffer
#define CHUNKS_PER_BLOCK 2               // 64 KB of output per block
#define THREADS       256

__global__ void gaines_edge_tma_fill_kernel(float* __restrict__ out) {
    __shared__ __align__(128) float4 buf[CHUNK_BYTES / 16];  // 32 KB

    // Fill staging buffer with 1.0f: 8 float4 per thread.
    const float4 v = make_float4(1.0f, 1.0f, 1.0f, 1.0f);
#pragma unroll
    for (int j = 0; j < (CHUNK_BYTES / 16) / THREADS; j++) {
        buf[threadIdx.x + j * THREADS] = v;
    }
    __syncthreads();

    // Order generic-proxy STS before async-proxy TMA reads of SMEM.
    asm volatile("fence.proxy.async.shared::cta;" ::: "memory");

    if (threadIdx.x == 0) {
        uint32_t smem_addr;
        asm("{ .reg .u64 t; cvta.to.shared.u64 t, %1; cvt.u32.u64 %0, t; }"
            : "=r"(smem_addr) : "l"(buf));

        uint64_t gbase = (uint64_t)out
                       + (uint64_t)blockIdx.x * (CHUNK_BYTES * CHUNKS_PER_BLOCK);
#pragma unroll
        for (int c = 0; c < CHUNKS_PER_BLOCK; c++) {
            uint64_t gaddr = gbase + (uint64_t)c * CHUNK_BYTES;
            asm volatile(
                "cp.async.bulk.global.shared::cta.bulk_group [%0], [%1], %2;"
                :: "l"(gaddr), "r"(smem_addr), "n"(CHUNK_BYTES)
                : "memory");
        }
        asm volatile("cp.async.bulk.commit_group;" ::: "memory");
        // Full completion (writes issued to the memory system) before exit.
        asm volatile("cp.async.bulk.wait_group 0;" ::: "memory");
    }
}

extern "C" void kernel_launch(void* const* d_in, const int* in_sizes, int n_in,
                              void* d_out, int out_size) {
    float* out = (float*)d_out;

    // 67,108,864 B total / 64 KB per block = 1024 blocks (exact).
    int total_bytes = out_size * 4;
    int blocks = total_bytes / (CHUNK_BYTES * CHUNKS_PER_BLOCK);

    gaines_edge_tma_fill_kernel<<<blocks, THREADS>>>(out);
}